// round 15
// baseline (speedup 1.0000x reference)
#include <cuda_runtime.h>
#include <math.h>

#define N_NODES 50000
#define N_EDGES 400000
#define F_DIM   128
#define N_TYPES 100
#define N_RBF   20
#define CUTOFF  5.0f
#define F3      (3 * F_DIM)   // 384

#define SCAN_B  256
#define SCAN_NB ((N_NODES + SCAN_B - 1) / SCAN_B)   // 196
#define HIST_NB ((N_EDGES + 255) / 256)             // 1563
#define PHI_NB  (N_TYPES / 2)                       // 50

#define NPB     50                                  // nodes per main block
#define MAIN_NB (N_NODES / NPB)                     // 1000 (divides exactly)
#define E_MAX   (N_EDGES + 3 * N_NODES + 16)        // padded edge capacity

typedef unsigned long long ull;

// -------- device scratch (no allocations allowed; zero-initialized at load) --------
__device__ int   g_count[N_NODES];        // re-zeroed by scan role each call
__device__ int   g_start[N_NODES + 1];    // PADDED segment starts (multiples of 4)
__device__ int   g_cursor[N_NODES];
__device__ ull   g_scan_state[SCAN_NB];   // re-zeroed by main each call
__device__ int   g_pub[SCAN_NB];          // per-scan-block publish flags; re-zeroed by main
__device__ float g_phi[(N_TYPES + 1) * F3];  // row N_TYPES stays all-zero (pad sentinel)

// per-edge packed row (dst-sorted order), 32 bytes:
// [0]=sin(a) [1]=cos(a) [2]=1/dist [3]=rd.x | [4]=rd.y [5]=rd.z [6]=src bits [7]=typ bits
struct __align__(16) EdgeRow { float v[8]; };
__device__ EdgeRow g_edat[E_MAX];         // 13.9 MB

// ---------------------------------------------------------
// Launch 0 (pre): hist blocks count edge_dst; phi blocks compute the MLP table.
__global__ void pre_kernel(const int* __restrict__ edge_dst,
                           const float* __restrict__ emb_table,
                           const float* __restrict__ w1, const float* __restrict__ b1,
                           const float* __restrict__ w2, const float* __restrict__ b2) {
    if (blockIdx.x < HIST_NB) {
        int e = blockIdx.x * 256 + threadIdx.x;
        if (e < N_EDGES) atomicAdd(&g_count[edge_dst[e]], 1);
        return;
    }
    // phi: 2 atom types per block (each 128-thread half does one type)
    int bb = blockIdx.x - HIST_NB;          // 0..49
    int half = threadIdx.x >> 7;            // 0/1
    int t = bb * 2 + half;                  // atom type
    int f = threadIdx.x & 127;
    __shared__ float es[2][F_DIM];
    __shared__ float hs[2][F_DIM];
    es[half][f] = emb_table[t * F_DIM + f];
    __syncthreads();
    float h = b1[f];
#pragma unroll 8
    for (int k = 0; k < F_DIM; k++)
        h = fmaf(es[half][k], w1[k * F_DIM + f], h);
    h = h / (1.0f + expf(-h));   // silu
    hs[half][f] = h;
    __syncthreads();
    float o0 = b2[f], o1 = b2[F_DIM + f], o2 = b2[2 * F_DIM + f];
#pragma unroll 8
    for (int k = 0; k < F_DIM; k++) {
        float hk = hs[half][k];
        const float* w2r = w2 + k * F3;
        o0 = fmaf(hk, w2r[f],             o0);
        o1 = fmaf(hk, w2r[F_DIM + f],     o1);
        o2 = fmaf(hk, w2r[2 * F_DIM + f], o2);
    }
    g_phi[t * F3 + f]             = o0;
    g_phi[t * F3 + F_DIM + f]     = o1;
    g_phi[t * F3 + 2 * F_DIM + f] = o2;
}

// ---------------------------------------------------------
// Launch 1 (fused): blocks [0, SCAN_NB) run the decoupled-lookback scan of
// padded counts and PUBLISH per-block flags; blocks [SCAN_NB, ...) compute
// edge geometry immediately (independent of scan), then spin on the dst's
// publish flag before claiming a slot and storing the 32B row.
// Deadlock-free: scan blocks have the lowest ids -> all dispatched in wave 1
// (in-order dispatch) and depend only on lower-id scan blocks.
__global__ void scansg_kernel(const float* __restrict__ pos,
                              const int*   __restrict__ z,
                              const int*   __restrict__ edge_src,
                              const int*   __restrict__ edge_dst) {
    if (blockIdx.x < SCAN_NB) {
        // ---- scan role ----
        __shared__ int wsum[SCAN_B / 32];
        __shared__ int s_prefix;
        int t = threadIdx.x;
        int b = blockIdx.x;
        int i = b * SCAN_B + t;
        int v = 0, pc = 0;
        if (i < N_NODES) {
            v = g_count[i];
            g_count[i] = 0;
            pc = (v + 3) & ~3;
        }

        int sv = pc;
        for (int off = 1; off < 32; off <<= 1) {
            int u = __shfl_up_sync(0xffffffffu, sv, off);
            if ((t & 31) >= off) sv += u;
        }
        if ((t & 31) == 31) wsum[t >> 5] = sv;
        __syncthreads();
        if (t < SCAN_B / 32) {
            int s = wsum[t];
            for (int off = 1; off < SCAN_B / 32; off <<= 1) {
                int u = __shfl_up_sync(0xffu, s, off);
                if (t >= off) s += u;
            }
            wsum[t] = s;
        }
        __syncthreads();
        int warp = t >> 5;
        int incl = sv + ((warp > 0) ? wsum[warp - 1] : 0);
        int total = wsum[SCAN_B / 32 - 1];

        if (t == 0) {
            if (b == 0) {
                atomicExch(&g_scan_state[0], ((ull)total << 2) | 2ULL);
                s_prefix = 0;
            } else {
                atomicExch(&g_scan_state[b], ((ull)total << 2) | 1ULL);
                int prefix = 0;
                int j = b - 1;
                while (j >= 0) {
                    ull st;
                    do { st = atomicAdd(&g_scan_state[j], 0ULL); } while ((st & 3ULL) == 0ULL);
                    prefix += (int)(st >> 2);
                    if ((st & 3ULL) == 2ULL) break;
                    j--;
                }
                atomicExch(&g_scan_state[b], ((ull)(prefix + total) << 2) | 2ULL);
                s_prefix = prefix;
            }
            if (b == SCAN_NB - 1) g_start[N_NODES] = s_prefix + total;
        }
        __syncthreads();
        int excl = s_prefix + incl - pc;
        if (i < N_NODES) {
            g_start[i]  = excl;
            g_cursor[i] = excl;
            // inert pad rows: sin=cos=inv=0 -> rbf all zero; typ=N_TYPES (zero phi row)
            for (int j = excl + v; j < excl + pc; j++) {
                float4* d4 = reinterpret_cast<float4*>(g_edat[j].v);
                d4[0] = make_float4(0.f, 0.f, 0.f, 0.f);
                d4[1] = make_float4(0.f, 0.f, 0.f, __int_as_float(N_TYPES));
            }
        }
        // publish: cursor/start/pads for this block's 256 nodes are visible
        __syncthreads();
        __threadfence();
        if (t == 0) atomicExch(&g_pub[b], 1);
        return;
    }

    // ---- sg role ----
    int e = (blockIdx.x - SCAN_NB) * 256 + threadIdx.x;
    if (e >= N_EDGES) return;
    int s = __ldg(&edge_src[e]);
    int d = __ldg(&edge_dst[e]);
    int ty = __ldg(&z[s]);
    float rx = __ldg(&pos[d * 3 + 0]) - __ldg(&pos[s * 3 + 0]);
    float ry = __ldg(&pos[d * 3 + 1]) - __ldg(&pos[s * 3 + 1]);
    float rz = __ldg(&pos[d * 3 + 2]) - __ldg(&pos[s * 3 + 2]);
    float dist = sqrtf(rx * rx + ry * ry + rz * rz);
    float inv  = 1.0f / dist;
    float a = 3.14159265358979323846f * dist * (1.0f / CUTOFF);
    float s1, c1;
    sincosf(a, &s1, &c1);

    // wait for the scan block owning dst d, then claim slot
    int blk = d >> 8;     // SCAN_B = 256
    while (atomicAdd(&g_pub[blk], 0) == 0) __nanosleep(64);
    int p = atomicAdd(&g_cursor[d], 1);

    float4* dst4 = reinterpret_cast<float4*>(g_edat[p].v);
    dst4[0] = make_float4(s1, c1, inv, rx * dist);
    dst4[1] = make_float4(ry * dist, rz * dist, __int_as_float(s), __int_as_float(ty));
}

// ---------------------------------------------------------
// Launch 2 (PROFILED): main — proven R12 body, NPB=50.
// Block 0 also re-zeroes scan bookkeeping for the next call.
__global__ __launch_bounds__(128, 4)
void main_kernel(const float* __restrict__ eq,
                 const float* __restrict__ emb_table,
                 const float* __restrict__ w_rbf,
                 const float* __restrict__ b_rbf,
                 const int*   __restrict__ z,
                 float* __restrict__ out_emb,
                 float* __restrict__ out_eq) {
    int f = threadIdx.x;
    int nb0 = blockIdx.x * NPB;

    if (blockIdx.x == 0) {
        for (int i = f; i < SCAN_NB; i += 128) {
            g_scan_state[i] = 0ULL;
            g_pub[i] = 0;
        }
    }

    __shared__ int s_bnd[NPB + 1];
    if (f <= NPB) s_bnd[f] = g_start[nb0 + f];

    // per-thread w_rbf columns in registers (60 regs) — once per 50 nodes
    float wr0[N_RBF], wr1[N_RBF], wr2[N_RBF];
#pragma unroll
    for (int k = 0; k < N_RBF; k++) {
        const float* row = w_rbf + k * F3;
        wr0[k] = row[f];
        wr1[k] = row[F_DIM + f];
        wr2[k] = row[2 * F_DIM + f];
    }
    const float br0 = b_rbf[f], br1 = b_rbf[F_DIM + f], br2 = b_rbf[2 * F_DIM + f];

    __shared__ __align__(16) float sh_rbf[N_RBF][128];
    __shared__ __align__(16) float sh_rd0[128], sh_rd1[128], sh_rd2[128];
    __shared__ __align__(16) int   sh_src[128];
    __shared__ __align__(16) int   sh_typ[128];

    __syncthreads();
    const int eAll0 = s_bnd[0];
    const int eAll1 = s_bnd[NPB];
    int nd = 0;   // local node index 0..NPB-1
    float acc0 = 0.f, aq0 = 0.f, aq1 = 0.f, aq2 = 0.f;

    for (int base = eAll0; base < eAll1; base += 128) {
        int nch = min(128, eAll1 - base);
        // phase 1: load 32B row, regenerate rbf via recurrence, stage transposed
        if (f < nch) {
            const float4* row = reinterpret_cast<const float4*>(g_edat[base + f].v);
            float4 A = __ldg(row + 0);
            float4 B = __ldg(row + 1);
            float twoc = 2.0f * A.y;
            float inv  = A.z;
            float sp = 0.0f, sc = A.x;     // sin(0), sin(a)
#pragma unroll
            for (int k = 0; k < N_RBF; k++) {
                sh_rbf[k][f] = sc * inv;
                float nx = twoc * sc - sp;
                sp = sc; sc = nx;
            }
            sh_rd0[f] = A.w;
            sh_rd1[f] = B.x;
            sh_rd2[f] = B.y;
            sh_src[f] = __float_as_int(B.z);
            sh_typ[f] = __float_as_int(B.w);
        }
        __syncthreads();

        // phase 2: walk node runs inside this chunk (all runs quad-aligned)
        int ec = 0;
        while (ec < nch) {
            int ndend = s_bnd[nd + 1];                       // global padded end
            int run = min(ndend - base, nch) - ec;           // multiple of 4
            for (int e = ec; e < ec + run; e += 4) {
                int4 s4 = *reinterpret_cast<const int4*>(&sh_src[e]);
                int4 t4 = *reinterpret_cast<const int4*>(&sh_typ[e]);
                const float* phA = g_phi + t4.x * F3;
                const float* phB = g_phi + t4.y * F3;
                const float* phC = g_phi + t4.z * F3;
                const float* phD = g_phi + t4.w * F3;
                float pA0 = phA[f], pA1 = phA[F_DIM + f], pA2 = phA[2 * F_DIM + f];
                float pB0 = phB[f], pB1 = phB[F_DIM + f], pB2 = phB[2 * F_DIM + f];
                float pC0 = phC[f], pC1 = phC[F_DIM + f], pC2 = phC[2 * F_DIM + f];
                float pD0 = phD[f], pD1 = phD[F_DIM + f], pD2 = phD[2 * F_DIM + f];
                const float* eqA = eq + (size_t)s4.x * F3 + f * 3;
                const float* eqB = eq + (size_t)s4.y * F3 + f * 3;
                const float* eqC = eq + (size_t)s4.z * F3 + f * 3;
                const float* eqD = eq + (size_t)s4.w * F3 + f * 3;
                float eA0 = eqA[0], eA1 = eqA[1], eA2 = eqA[2];
                float eB0 = eqB[0], eB1 = eqB[1], eB2 = eqB[2];
                float eC0 = eqC[0], eC1 = eqC[1], eC2 = eqC[2];
                float eD0 = eqD[0], eD1 = eqD[1], eD2 = eqD[2];
                float4 rdx = *reinterpret_cast<const float4*>(&sh_rd0[e]);
                float4 rdy = *reinterpret_cast<const float4*>(&sh_rd1[e]);
                float4 rdz = *reinterpret_cast<const float4*>(&sh_rd2[e]);

                float WA0 = br0, WA1 = br1, WA2 = br2;
                float WB0 = br0, WB1 = br1, WB2 = br2;
                float WC0 = br0, WC1 = br1, WC2 = br2;
                float WD0 = br0, WD1 = br1, WD2 = br2;
#pragma unroll
                for (int k = 0; k < N_RBF; k++) {
                    float4 r4 = *reinterpret_cast<const float4*>(&sh_rbf[k][e]);
                    WA0 = fmaf(r4.x, wr0[k], WA0);
                    WA1 = fmaf(r4.x, wr1[k], WA1);
                    WA2 = fmaf(r4.x, wr2[k], WA2);
                    WB0 = fmaf(r4.y, wr0[k], WB0);
                    WB1 = fmaf(r4.y, wr1[k], WB1);
                    WB2 = fmaf(r4.y, wr2[k], WB2);
                    WC0 = fmaf(r4.z, wr0[k], WC0);
                    WC1 = fmaf(r4.z, wr1[k], WC1);
                    WC2 = fmaf(r4.z, wr2[k], WC2);
                    WD0 = fmaf(r4.w, wr0[k], WD0);
                    WD1 = fmaf(r4.w, wr1[k], WD1);
                    WD2 = fmaf(r4.w, wr2[k], WD2);
                }
                float sA1 = pA1 * WA1, sA2 = pA2 * WA2;
                float sB1 = pB1 * WB1, sB2 = pB2 * WB2;
                float sC1 = pC1 * WC1, sC2 = pC2 * WC2;
                float sD1 = pD1 * WD1, sD2 = pD2 * WD2;
                acc0 = fmaf(pA0, WA0, acc0);
                acc0 = fmaf(pB0, WB0, acc0);
                acc0 = fmaf(pC0, WC0, acc0);
                acc0 = fmaf(pD0, WD0, acc0);
                aq0 = fmaf(eA0, sA1, fmaf(sA2, rdx.x, aq0));
                aq1 = fmaf(eA1, sA1, fmaf(sA2, rdy.x, aq1));
                aq2 = fmaf(eA2, sA1, fmaf(sA2, rdz.x, aq2));
                aq0 = fmaf(eB0, sB1, fmaf(sB2, rdx.y, aq0));
                aq1 = fmaf(eB1, sB1, fmaf(sB2, rdy.y, aq1));
                aq2 = fmaf(eB2, sB1, fmaf(sB2, rdz.y, aq2));
                aq0 = fmaf(eC0, sC1, fmaf(sC2, rdx.z, aq0));
                aq1 = fmaf(eC1, sC1, fmaf(sC2, rdy.z, aq1));
                aq2 = fmaf(eC2, sC1, fmaf(sC2, rdz.z, aq2));
                aq0 = fmaf(eD0, sD1, fmaf(sD2, rdx.w, aq0));
                aq1 = fmaf(eD1, sD1, fmaf(sD2, rdy.w, aq1));
                aq2 = fmaf(eD2, sD1, fmaf(sD2, rdz.w, aq2));
            }
            ec += run;
            if (base + ec == ndend) {
                // close node nb0+nd
                int node = nb0 + nd;
                int zi = __ldg(&z[node]);
                out_emb[node * F_DIM + f] = emb_table[zi * F_DIM + f] + acc0;
                const float* ei = eq     + (size_t)node * F3 + f * 3;
                float*       oe = out_eq + (size_t)node * F3 + f * 3;
                oe[0] = ei[0] + aq0;
                oe[1] = ei[1] + aq1;
                oe[2] = ei[2] + aq2;
                acc0 = aq0 = aq1 = aq2 = 0.f;
                nd++;
            }
        }
        __syncthreads();
    }

    // flush trailing empty nodes (zero-degree): out = input
    while (nd < NPB) {
        int node = nb0 + nd;
        int zi = __ldg(&z[node]);
        out_emb[node * F_DIM + f] = emb_table[zi * F_DIM + f];
        const float* ei = eq     + (size_t)node * F3 + f * 3;
        float*       oe = out_eq + (size_t)node * F3 + f * 3;
        oe[0] = ei[0];
        oe[1] = ei[1];
        oe[2] = ei[2];
        nd++;
    }
}

// ---------------------------------------------------------
extern "C" void kernel_launch(void* const* d_in, const int* in_sizes, int n_in,
                              void* d_out, int out_size) {
    const float* pos       = (const float*)d_in[0];
    const float* eq        = (const float*)d_in[1];
    const float* emb_table = (const float*)d_in[2];
    const float* w_phi1    = (const float*)d_in[3];
    const float* b_phi1    = (const float*)d_in[4];
    const float* w_phi2    = (const float*)d_in[5];
    const float* b_phi2    = (const float*)d_in[6];
    const float* w_rbf     = (const float*)d_in[7];
    const float* b_rbf     = (const float*)d_in[8];
    const int*   z         = (const int*)d_in[9];
    const int*   edge_src  = (const int*)d_in[10];
    const int*   edge_dst  = (const int*)d_in[11];

    float* out     = (float*)d_out;
    float* out_emb = out;                                  // [N, 128]
    float* out_eq  = out + (size_t)N_NODES * F_DIM;        // [N, 128, 3]

    pre_kernel<<<HIST_NB + PHI_NB, 256>>>(edge_dst, emb_table, w_phi1, b_phi1,
                                          w_phi2, b_phi2);
    scansg_kernel<<<SCAN_NB + HIST_NB, 256>>>(pos, z, edge_src, edge_dst);
    main_kernel<<<MAIN_NB, 128>>>(eq, emb_table, w_rbf, b_rbf, z,
                                  out_emb, out_eq);
}

// round 16
// speedup vs baseline: 4.0687x; 4.0687x over previous
#include <cuda_runtime.h>
#include <math.h>

#define N_NODES 50000
#define N_EDGES 400000
#define F_DIM   128
#define N_TYPES 100
#define N_RBF   20
#define CUTOFF  5.0f
#define F3      (3 * F_DIM)   // 384

#define SCAN_B  256
#define SCAN_NB ((N_NODES + SCAN_B - 1) / SCAN_B)   // 196
#define HIST_NB ((N_EDGES + 255) / 256)             // 1563
#define HIST4_NB ((N_EDGES / 4 + 255) / 256)        // 391 (N_EDGES % 4 == 0)
#define PHI_NB  (N_TYPES / 2)                       // 50

#define NPB     50                                  // nodes per main block
#define MAIN_NB (N_NODES / NPB)                     // 1000 (divides exactly)
#define E_MAX   (N_EDGES + 3 * N_NODES + 16)        // padded edge capacity

typedef unsigned long long ull;

// -------- device scratch (no allocations allowed; zero-initialized at load) --------
__device__ int   g_count[N_NODES];        // re-zeroed by scan_kernel each call
__device__ int   g_start[N_NODES + 1];    // PADDED segment starts (multiples of 4)
__device__ int   g_cursor[N_NODES];
__device__ ull   g_scan_state[SCAN_NB];   // re-zeroed by sg_kernel each call
__device__ float g_phi[(N_TYPES + 1) * F3];  // row N_TYPES stays all-zero (pad sentinel)

// per-edge packed row (dst-sorted order), 32 bytes:
// [0]=sin(a) [1]=cos(a) [2]=1/dist [3]=rd.x | [4]=rd.y [5]=rd.z [6]=src bits [7]=typ bits
struct __align__(16) EdgeRow { float v[8]; };
__device__ EdgeRow g_edat[E_MAX];         // 13.9 MB

// ---------------------------------------------------------
// Launch 0 (pre): hist blocks count edge_dst (4 edges/thread via int4 -> MLP=4);
// phi blocks compute the MLP table.
__global__ void pre_kernel(const int* __restrict__ edge_dst,
                           const float* __restrict__ emb_table,
                           const float* __restrict__ w1, const float* __restrict__ b1,
                           const float* __restrict__ w2, const float* __restrict__ b2) {
    if (blockIdx.x < HIST4_NB) {
        int i = blockIdx.x * 256 + threadIdx.x;
        if (i < N_EDGES / 4) {
            int4 d4 = __ldg(reinterpret_cast<const int4*>(edge_dst) + i);
            atomicAdd(&g_count[d4.x], 1);
            atomicAdd(&g_count[d4.y], 1);
            atomicAdd(&g_count[d4.z], 1);
            atomicAdd(&g_count[d4.w], 1);
        }
        return;
    }
    // phi: 2 atom types per block (each 128-thread half does one type)
    int bb = blockIdx.x - HIST4_NB;         // 0..49
    int half = threadIdx.x >> 7;            // 0/1
    int t = bb * 2 + half;                  // atom type
    int f = threadIdx.x & 127;
    __shared__ float es[2][F_DIM];
    __shared__ float hs[2][F_DIM];
    es[half][f] = emb_table[t * F_DIM + f];
    __syncthreads();
    float h = b1[f];
#pragma unroll 8
    for (int k = 0; k < F_DIM; k++)
        h = fmaf(es[half][k], w1[k * F_DIM + f], h);
    h = h / (1.0f + expf(-h));   // silu
    hs[half][f] = h;
    __syncthreads();
    float o0 = b2[f], o1 = b2[F_DIM + f], o2 = b2[2 * F_DIM + f];
#pragma unroll 8
    for (int k = 0; k < F_DIM; k++) {
        float hk = hs[half][k];
        const float* w2r = w2 + k * F3;
        o0 = fmaf(hk, w2r[f],             o0);
        o1 = fmaf(hk, w2r[F_DIM + f],     o1);
        o2 = fmaf(hk, w2r[2 * F_DIM + f], o2);
    }
    g_phi[t * F3 + f]             = o0;
    g_phi[t * F3 + F_DIM + f]     = o1;
    g_phi[t * F3 + 2 * F_DIM + f] = o2;
}

// ---------------------------------------------------------
// Launch 1: decoupled-lookback exclusive scan of PADDED counts
// ((cnt+3)&~3) -> g_start, g_cursor. Re-zeroes g_count; writes inert pad rows.
__global__ void scan_kernel() {
    __shared__ int wsum[SCAN_B / 32];
    __shared__ int s_prefix;
    int t = threadIdx.x;
    int b = blockIdx.x;
    int i = b * SCAN_B + t;
    int v = 0, pc = 0;
    if (i < N_NODES) {
        v = g_count[i];
        g_count[i] = 0;
        pc = (v + 3) & ~3;
    }

    int sv = pc;
    for (int off = 1; off < 32; off <<= 1) {
        int u = __shfl_up_sync(0xffffffffu, sv, off);
        if ((t & 31) >= off) sv += u;
    }
    if ((t & 31) == 31) wsum[t >> 5] = sv;
    __syncthreads();
    if (t < SCAN_B / 32) {
        int s = wsum[t];
        for (int off = 1; off < SCAN_B / 32; off <<= 1) {
            int u = __shfl_up_sync(0xffu, s, off);
            if (t >= off) s += u;
        }
        wsum[t] = s;
    }
    __syncthreads();
    int warp = t >> 5;
    int incl = sv + ((warp > 0) ? wsum[warp - 1] : 0);
    int total = wsum[SCAN_B / 32 - 1];

    if (t == 0) {
        if (b == 0) {
            atomicExch(&g_scan_state[0], ((ull)total << 2) | 2ULL);
            s_prefix = 0;
        } else {
            atomicExch(&g_scan_state[b], ((ull)total << 2) | 1ULL);
            int prefix = 0;
            int j = b - 1;
            while (j >= 0) {
                ull st;
                do { st = atomicAdd(&g_scan_state[j], 0ULL); } while ((st & 3ULL) == 0ULL);
                prefix += (int)(st >> 2);
                if ((st & 3ULL) == 2ULL) break;
                j--;
            }
            atomicExch(&g_scan_state[b], ((ull)(prefix + total) << 2) | 2ULL);
            s_prefix = prefix;
        }
        if (b == SCAN_NB - 1) g_start[N_NODES] = s_prefix + total;
    }
    __syncthreads();
    int excl = s_prefix + incl - pc;
    if (i < N_NODES) {
        g_start[i]  = excl;
        g_cursor[i] = excl;
        // inert pad rows: sin=cos=inv=0 -> rbf all zero; typ=N_TYPES (zero phi row)
        for (int j = excl + v; j < excl + pc; j++) {
            float4* d4 = reinterpret_cast<float4*>(g_edat[j].v);
            d4[0] = make_float4(0.f, 0.f, 0.f, 0.f);
            d4[1] = make_float4(0.f, 0.f, 0.f, __int_as_float(N_TYPES));
        }
    }
}

// ---------------------------------------------------------
// Launch 2: fused scatter + geometry (32B rows); also re-zeroes g_scan_state.
__global__ void sg_kernel(const float* __restrict__ pos,
                          const int*   __restrict__ z,
                          const int*   __restrict__ edge_src,
                          const int*   __restrict__ edge_dst) {
    int e = blockIdx.x * blockDim.x + threadIdx.x;
    if (e < SCAN_NB) g_scan_state[e] = 0ULL;
    if (e >= N_EDGES) return;
    int s = __ldg(&edge_src[e]);
    int d = __ldg(&edge_dst[e]);
    int p = atomicAdd(&g_cursor[d], 1);
    int ty = __ldg(&z[s]);
    float rx = __ldg(&pos[d * 3 + 0]) - __ldg(&pos[s * 3 + 0]);
    float ry = __ldg(&pos[d * 3 + 1]) - __ldg(&pos[s * 3 + 1]);
    float rz = __ldg(&pos[d * 3 + 2]) - __ldg(&pos[s * 3 + 2]);
    float dist = sqrtf(rx * rx + ry * ry + rz * rz);
    float inv  = 1.0f / dist;

    float a = 3.14159265358979323846f * dist * (1.0f / CUTOFF);
    float s1, c1;
    sincosf(a, &s1, &c1);

    float4* dst4 = reinterpret_cast<float4*>(g_edat[p].v);
    dst4[0] = make_float4(s1, c1, inv, rx * dist);
    dst4[1] = make_float4(ry * dist, rz * dist, __int_as_float(s), __int_as_float(ty));
}

// ---------------------------------------------------------
// Launch 3 (PROFILED): main — proven R12 body, NPB=50.
__global__ __launch_bounds__(128, 4)
void main_kernel(const float* __restrict__ eq,
                 const float* __restrict__ emb_table,
                 const float* __restrict__ w_rbf,
                 const float* __restrict__ b_rbf,
                 const int*   __restrict__ z,
                 float* __restrict__ out_emb,
                 float* __restrict__ out_eq) {
    int f = threadIdx.x;
    int nb0 = blockIdx.x * NPB;

    __shared__ int s_bnd[NPB + 1];
    if (f <= NPB) s_bnd[f] = g_start[nb0 + f];

    // per-thread w_rbf columns in registers (60 regs) — once per 50 nodes
    float wr0[N_RBF], wr1[N_RBF], wr2[N_RBF];
#pragma unroll
    for (int k = 0; k < N_RBF; k++) {
        const float* row = w_rbf + k * F3;
        wr0[k] = row[f];
        wr1[k] = row[F_DIM + f];
        wr2[k] = row[2 * F_DIM + f];
    }
    const float br0 = b_rbf[f], br1 = b_rbf[F_DIM + f], br2 = b_rbf[2 * F_DIM + f];

    __shared__ __align__(16) float sh_rbf[N_RBF][128];
    __shared__ __align__(16) float sh_rd0[128], sh_rd1[128], sh_rd2[128];
    __shared__ __align__(16) int   sh_src[128];
    __shared__ __align__(16) int   sh_typ[128];

    __syncthreads();
    const int eAll0 = s_bnd[0];
    const int eAll1 = s_bnd[NPB];
    int nd = 0;   // local node index 0..NPB-1
    float acc0 = 0.f, aq0 = 0.f, aq1 = 0.f, aq2 = 0.f;

    for (int base = eAll0; base < eAll1; base += 128) {
        int nch = min(128, eAll1 - base);
        // phase 1: load 32B row, regenerate rbf via recurrence, stage transposed
        if (f < nch) {
            const float4* row = reinterpret_cast<const float4*>(g_edat[base + f].v);
            float4 A = __ldg(row + 0);
            float4 B = __ldg(row + 1);
            float twoc = 2.0f * A.y;
            float inv  = A.z;
            float sp = 0.0f, sc = A.x;     // sin(0), sin(a)
#pragma unroll
            for (int k = 0; k < N_RBF; k++) {
                sh_rbf[k][f] = sc * inv;
                float nx = twoc * sc - sp;
                sp = sc; sc = nx;
            }
            sh_rd0[f] = A.w;
            sh_rd1[f] = B.x;
            sh_rd2[f] = B.y;
            sh_src[f] = __float_as_int(B.z);
            sh_typ[f] = __float_as_int(B.w);
        }
        __syncthreads();

        // phase 2: walk node runs inside this chunk (all runs quad-aligned)
        int ec = 0;
        while (ec < nch) {
            int ndend = s_bnd[nd + 1];                       // global padded end
            int run = min(ndend - base, nch) - ec;           // multiple of 4
            for (int e = ec; e < ec + run; e += 4) {
                int4 s4 = *reinterpret_cast<const int4*>(&sh_src[e]);
                int4 t4 = *reinterpret_cast<const int4*>(&sh_typ[e]);
                const float* phA = g_phi + t4.x * F3;
                const float* phB = g_phi + t4.y * F3;
                const float* phC = g_phi + t4.z * F3;
                const float* phD = g_phi + t4.w * F3;
                float pA0 = phA[f], pA1 = phA[F_DIM + f], pA2 = phA[2 * F_DIM + f];
                float pB0 = phB[f], pB1 = phB[F_DIM + f], pB2 = phB[2 * F_DIM + f];
                float pC0 = phC[f], pC1 = phC[F_DIM + f], pC2 = phC[2 * F_DIM + f];
                float pD0 = phD[f], pD1 = phD[F_DIM + f], pD2 = phD[2 * F_DIM + f];
                const float* eqA = eq + (size_t)s4.x * F3 + f * 3;
                const float* eqB = eq + (size_t)s4.y * F3 + f * 3;
                const float* eqC = eq + (size_t)s4.z * F3 + f * 3;
                const float* eqD = eq + (size_t)s4.w * F3 + f * 3;
                float eA0 = eqA[0], eA1 = eqA[1], eA2 = eqA[2];
                float eB0 = eqB[0], eB1 = eqB[1], eB2 = eqB[2];
                float eC0 = eqC[0], eC1 = eqC[1], eC2 = eqC[2];
                float eD0 = eqD[0], eD1 = eqD[1], eD2 = eqD[2];
                float4 rdx = *reinterpret_cast<const float4*>(&sh_rd0[e]);
                float4 rdy = *reinterpret_cast<const float4*>(&sh_rd1[e]);
                float4 rdz = *reinterpret_cast<const float4*>(&sh_rd2[e]);

                float WA0 = br0, WA1 = br1, WA2 = br2;
                float WB0 = br0, WB1 = br1, WB2 = br2;
                float WC0 = br0, WC1 = br1, WC2 = br2;
                float WD0 = br0, WD1 = br1, WD2 = br2;
#pragma unroll
                for (int k = 0; k < N_RBF; k++) {
                    float4 r4 = *reinterpret_cast<const float4*>(&sh_rbf[k][e]);
                    WA0 = fmaf(r4.x, wr0[k], WA0);
                    WA1 = fmaf(r4.x, wr1[k], WA1);
                    WA2 = fmaf(r4.x, wr2[k], WA2);
                    WB0 = fmaf(r4.y, wr0[k], WB0);
                    WB1 = fmaf(r4.y, wr1[k], WB1);
                    WB2 = fmaf(r4.y, wr2[k], WB2);
                    WC0 = fmaf(r4.z, wr0[k], WC0);
                    WC1 = fmaf(r4.z, wr1[k], WC1);
                    WC2 = fmaf(r4.z, wr2[k], WC2);
                    WD0 = fmaf(r4.w, wr0[k], WD0);
                    WD1 = fmaf(r4.w, wr1[k], WD1);
                    WD2 = fmaf(r4.w, wr2[k], WD2);
                }
                float sA1 = pA1 * WA1, sA2 = pA2 * WA2;
                float sB1 = pB1 * WB1, sB2 = pB2 * WB2;
                float sC1 = pC1 * WC1, sC2 = pC2 * WC2;
                float sD1 = pD1 * WD1, sD2 = pD2 * WD2;
                acc0 = fmaf(pA0, WA0, acc0);
                acc0 = fmaf(pB0, WB0, acc0);
                acc0 = fmaf(pC0, WC0, acc0);
                acc0 = fmaf(pD0, WD0, acc0);
                aq0 = fmaf(eA0, sA1, fmaf(sA2, rdx.x, aq0));
                aq1 = fmaf(eA1, sA1, fmaf(sA2, rdy.x, aq1));
                aq2 = fmaf(eA2, sA1, fmaf(sA2, rdz.x, aq2));
                aq0 = fmaf(eB0, sB1, fmaf(sB2, rdx.y, aq0));
                aq1 = fmaf(eB1, sB1, fmaf(sB2, rdy.y, aq1));
                aq2 = fmaf(eB2, sB1, fmaf(sB2, rdz.y, aq2));
                aq0 = fmaf(eC0, sC1, fmaf(sC2, rdx.z, aq0));
                aq1 = fmaf(eC1, sC1, fmaf(sC2, rdy.z, aq1));
                aq2 = fmaf(eC2, sC1, fmaf(sC2, rdz.z, aq2));
                aq0 = fmaf(eD0, sD1, fmaf(sD2, rdx.w, aq0));
                aq1 = fmaf(eD1, sD1, fmaf(sD2, rdy.w, aq1));
                aq2 = fmaf(eD2, sD1, fmaf(sD2, rdz.w, aq2));
            }
            ec += run;
            if (base + ec == ndend) {
                // close node nb0+nd
                int node = nb0 + nd;
                int zi = __ldg(&z[node]);
                out_emb[node * F_DIM + f] = emb_table[zi * F_DIM + f] + acc0;
                const float* ei = eq     + (size_t)node * F3 + f * 3;
                float*       oe = out_eq + (size_t)node * F3 + f * 3;
                oe[0] = ei[0] + aq0;
                oe[1] = ei[1] + aq1;
                oe[2] = ei[2] + aq2;
                acc0 = aq0 = aq1 = aq2 = 0.f;
                nd++;
            }
        }
        __syncthreads();
    }

    // flush trailing empty nodes (zero-degree): out = input
    while (nd < NPB) {
        int node = nb0 + nd;
        int zi = __ldg(&z[node]);
        out_emb[node * F_DIM + f] = emb_table[zi * F_DIM + f];
        const float* ei = eq     + (size_t)node * F3 + f * 3;
        float*       oe = out_eq + (size_t)node * F3 + f * 3;
        oe[0] = ei[0];
        oe[1] = ei[1];
        oe[2] = ei[2];
        nd++;
    }
}

// ---------------------------------------------------------
extern "C" void kernel_launch(void* const* d_in, const int* in_sizes, int n_in,
                              void* d_out, int out_size) {
    const float* pos       = (const float*)d_in[0];
    const float* eq        = (const float*)d_in[1];
    const float* emb_table = (const float*)d_in[2];
    const float* w_phi1    = (const float*)d_in[3];
    const float* b_phi1    = (const float*)d_in[4];
    const float* w_phi2    = (const float*)d_in[5];
    const float* b_phi2    = (const float*)d_in[6];
    const float* w_rbf     = (const float*)d_in[7];
    const float* b_rbf     = (const float*)d_in[8];
    const int*   z         = (const int*)d_in[9];
    const int*   edge_src  = (const int*)d_in[10];
    const int*   edge_dst  = (const int*)d_in[11];

    float* out     = (float*)d_out;
    float* out_emb = out;                                  // [N, 128]
    float* out_eq  = out + (size_t)N_NODES * F_DIM;        // [N, 128, 3]

    pre_kernel<<<HIST4_NB + PHI_NB, 256>>>(edge_dst, emb_table, w_phi1, b_phi1,
                                           w_phi2, b_phi2);
    scan_kernel<<<SCAN_NB, SCAN_B>>>();
    sg_kernel<<<HIST_NB, 256>>>(pos, z, edge_src, edge_dst);
    main_kernel<<<MAIN_NB, 128>>>(eq, emb_table, w_rbf, b_rbf, z,
                                  out_emb, out_eq);
}

// round 17
// speedup vs baseline: 4.2240x; 1.0382x over previous
#include <cuda_runtime.h>
#include <math.h>

#define N_NODES 50000
#define N_EDGES 400000
#define F_DIM   128
#define N_TYPES 100
#define N_RBF   20
#define CUTOFF  5.0f
#define F3      (3 * F_DIM)   // 384

#define SCAN_B  256
#define SCAN_NB ((N_NODES + SCAN_B - 1) / SCAN_B)   // 196
#define HIST_NB ((N_EDGES + 255) / 256)             // 1563
#define PHI_NB  (N_TYPES / 2)                       // 50

#define NPB     25                                  // nodes per main block
#define MAIN_NB (N_NODES / NPB)                     // 2000 (divides exactly)
#define E_MAX   (N_EDGES + 3 * N_NODES + 16)        // padded edge capacity

typedef unsigned long long ull;

// -------- device scratch (no allocations allowed; zero-initialized at load) --------
__device__ int   g_count[N_NODES];        // re-zeroed by scan_kernel each call
__device__ int   g_start[N_NODES + 1];    // PADDED segment starts (multiples of 4)
__device__ int   g_cursor[N_NODES];
__device__ ull   g_scan_state[SCAN_NB];   // re-zeroed by sg_kernel (post-sync) each call
__device__ float g_phi[(N_TYPES + 1) * F3];  // row N_TYPES stays all-zero (pad sentinel)

// per-edge packed row (dst-sorted order), 32 bytes:
// [0]=sin(a) [1]=cos(a) [2]=1/dist [3]=rd.x | [4]=rd.y [5]=rd.z [6]=src bits [7]=typ bits
struct __align__(16) EdgeRow { float v[8]; };
__device__ EdgeRow g_edat[E_MAX];         // 13.9 MB

// ---------------------------------------------------------
// Launch 0 (pre): hist blocks count edge_dst; phi blocks compute the MLP table.
// Triggers PDL completion early so scan's launch overlaps.
__global__ void pre_kernel(const int* __restrict__ edge_dst,
                           const float* __restrict__ emb_table,
                           const float* __restrict__ w1, const float* __restrict__ b1,
                           const float* __restrict__ w2, const float* __restrict__ b2) {
    cudaTriggerProgrammaticLaunchCompletion();
    if (blockIdx.x < HIST_NB) {
        int e = blockIdx.x * 256 + threadIdx.x;
        if (e < N_EDGES) atomicAdd(&g_count[edge_dst[e]], 1);
        return;
    }
    // phi: 2 atom types per block (each 128-thread half does one type)
    int bb = blockIdx.x - HIST_NB;          // 0..49
    int half = threadIdx.x >> 7;            // 0/1
    int t = bb * 2 + half;                  // atom type
    int f = threadIdx.x & 127;
    __shared__ float es[2][F_DIM];
    __shared__ float hs[2][F_DIM];
    es[half][f] = emb_table[t * F_DIM + f];
    __syncthreads();
    float h = b1[f];
#pragma unroll 8
    for (int k = 0; k < F_DIM; k++)
        h = fmaf(es[half][k], w1[k * F_DIM + f], h);
    h = h / (1.0f + expf(-h));   // silu
    hs[half][f] = h;
    __syncthreads();
    float o0 = b2[f], o1 = b2[F_DIM + f], o2 = b2[2 * F_DIM + f];
#pragma unroll 8
    for (int k = 0; k < F_DIM; k++) {
        float hk = hs[half][k];
        const float* w2r = w2 + k * F3;
        o0 = fmaf(hk, w2r[f],             o0);
        o1 = fmaf(hk, w2r[F_DIM + f],     o1);
        o2 = fmaf(hk, w2r[2 * F_DIM + f], o2);
    }
    g_phi[t * F3 + f]             = o0;
    g_phi[t * F3 + F_DIM + f]     = o1;
    g_phi[t * F3 + 2 * F_DIM + f] = o2;
}

// ---------------------------------------------------------
// Launch 1 (PDL): decoupled-lookback exclusive scan of PADDED counts
// ((cnt+3)&~3) -> g_start, g_cursor. Re-zeroes g_count; writes inert pad rows.
// Syncs on pre before reading g_count; triggers early so sg overlaps.
__global__ void scan_kernel() {
    cudaTriggerProgrammaticLaunchCompletion();
    cudaGridDependencySynchronize();       // pre's hist atomics complete

    __shared__ int wsum[SCAN_B / 32];
    __shared__ int s_prefix;
    int t = threadIdx.x;
    int b = blockIdx.x;
    int i = b * SCAN_B + t;
    int v = 0, pc = 0;
    if (i < N_NODES) {
        v = g_count[i];
        g_count[i] = 0;
        pc = (v + 3) & ~3;
    }

    int sv = pc;
    for (int off = 1; off < 32; off <<= 1) {
        int u = __shfl_up_sync(0xffffffffu, sv, off);
        if ((t & 31) >= off) sv += u;
    }
    if ((t & 31) == 31) wsum[t >> 5] = sv;
    __syncthreads();
    if (t < SCAN_B / 32) {
        int s = wsum[t];
        for (int off = 1; off < SCAN_B / 32; off <<= 1) {
            int u = __shfl_up_sync(0xffu, s, off);
            if (t >= off) s += u;
        }
        wsum[t] = s;
    }
    __syncthreads();
    int warp = t >> 5;
    int incl = sv + ((warp > 0) ? wsum[warp - 1] : 0);
    int total = wsum[SCAN_B / 32 - 1];

    if (t == 0) {
        if (b == 0) {
            atomicExch(&g_scan_state[0], ((ull)total << 2) | 2ULL);
            s_prefix = 0;
        } else {
            atomicExch(&g_scan_state[b], ((ull)total << 2) | 1ULL);
            int prefix = 0;
            int j = b - 1;
            while (j >= 0) {
                ull st;
                do { st = atomicAdd(&g_scan_state[j], 0ULL); } while ((st & 3ULL) == 0ULL);
                prefix += (int)(st >> 2);
                if ((st & 3ULL) == 2ULL) break;
                j--;
            }
            atomicExch(&g_scan_state[b], ((ull)(prefix + total) << 2) | 2ULL);
            s_prefix = prefix;
        }
        if (b == SCAN_NB - 1) g_start[N_NODES] = s_prefix + total;
    }
    __syncthreads();
    int excl = s_prefix + incl - pc;
    if (i < N_NODES) {
        g_start[i]  = excl;
        g_cursor[i] = excl;
        // inert pad rows: sin=cos=inv=0 -> rbf all zero; typ=N_TYPES (zero phi row)
        for (int j = excl + v; j < excl + pc; j++) {
            float4* d4 = reinterpret_cast<float4*>(g_edat[j].v);
            d4[0] = make_float4(0.f, 0.f, 0.f, 0.f);
            d4[1] = make_float4(0.f, 0.f, 0.f, __int_as_float(N_TYPES));
        }
    }
}

// ---------------------------------------------------------
// Launch 2 (PDL): fused scatter + geometry. Geometry (input gathers + sincos)
// runs PRE-sync, overlapping the scan; slot claim + store + scan-state reset
// run post-sync.
__global__ void sg_kernel(const float* __restrict__ pos,
                          const int*   __restrict__ z,
                          const int*   __restrict__ edge_src,
                          const int*   __restrict__ edge_dst) {
    cudaTriggerProgrammaticLaunchCompletion();
    int e = blockIdx.x * blockDim.x + threadIdx.x;

    int s = 0, d = 0, ty = 0;
    float s1 = 0.f, c1 = 0.f, inv = 0.f, rdx = 0.f, rdy = 0.f, rdz = 0.f;
    if (e < N_EDGES) {
        s = __ldg(&edge_src[e]);
        d = __ldg(&edge_dst[e]);
        ty = __ldg(&z[s]);
        float rx = __ldg(&pos[d * 3 + 0]) - __ldg(&pos[s * 3 + 0]);
        float ry = __ldg(&pos[d * 3 + 1]) - __ldg(&pos[s * 3 + 1]);
        float rz = __ldg(&pos[d * 3 + 2]) - __ldg(&pos[s * 3 + 2]);
        float dist = sqrtf(rx * rx + ry * ry + rz * rz);
        inv  = 1.0f / dist;
        float a = 3.14159265358979323846f * dist * (1.0f / CUTOFF);
        sincosf(a, &s1, &c1);
        rdx = rx * dist;
        rdy = ry * dist;
        rdz = rz * dist;
    }

    cudaGridDependencySynchronize();       // scan complete: cursor/start/pads ready

    if (e < SCAN_NB) g_scan_state[e] = 0ULL;   // safe now: scan done with it
    if (e >= N_EDGES) return;

    int p = atomicAdd(&g_cursor[d], 1);
    float4* dst4 = reinterpret_cast<float4*>(g_edat[p].v);
    dst4[0] = make_float4(s1, c1, inv, rdx);
    dst4[1] = make_float4(rdy, rdz, __int_as_float(s), __int_as_float(ty));
}

// ---------------------------------------------------------
// Launch 3 (PDL, PROFILED): main — proven R12 body, NPB=25. Weight preload
// (pure input reads) runs PRE-sync, hiding the cold-start bubble under sg.
__global__ __launch_bounds__(128, 4)
void main_kernel(const float* __restrict__ eq,
                 const float* __restrict__ emb_table,
                 const float* __restrict__ w_rbf,
                 const float* __restrict__ b_rbf,
                 const int*   __restrict__ z,
                 float* __restrict__ out_emb,
                 float* __restrict__ out_eq) {
    int f = threadIdx.x;
    int nb0 = blockIdx.x * NPB;

    // prelude: per-thread w_rbf columns in registers (60 regs) — inputs only
    float wr0[N_RBF], wr1[N_RBF], wr2[N_RBF];
#pragma unroll
    for (int k = 0; k < N_RBF; k++) {
        const float* row = w_rbf + k * F3;
        wr0[k] = row[f];
        wr1[k] = row[F_DIM + f];
        wr2[k] = row[2 * F_DIM + f];
    }
    const float br0 = b_rbf[f], br1 = b_rbf[F_DIM + f], br2 = b_rbf[2 * F_DIM + f];

    cudaGridDependencySynchronize();       // sg complete (transitively scan+pre)

    __shared__ int s_bnd[NPB + 1];
    if (f <= NPB) s_bnd[f] = g_start[nb0 + f];

    __shared__ __align__(16) float sh_rbf[N_RBF][128];
    __shared__ __align__(16) float sh_rd0[128], sh_rd1[128], sh_rd2[128];
    __shared__ __align__(16) int   sh_src[128];
    __shared__ __align__(16) int   sh_typ[128];

    __syncthreads();
    const int eAll0 = s_bnd[0];
    const int eAll1 = s_bnd[NPB];
    int nd = 0;   // local node index 0..NPB-1
    float acc0 = 0.f, aq0 = 0.f, aq1 = 0.f, aq2 = 0.f;

    for (int base = eAll0; base < eAll1; base += 128) {
        int nch = min(128, eAll1 - base);
        // phase 1: load 32B row, regenerate rbf via recurrence, stage transposed
        if (f < nch) {
            const float4* row = reinterpret_cast<const float4*>(g_edat[base + f].v);
            float4 A = __ldg(row + 0);
            float4 B = __ldg(row + 1);
            float twoc = 2.0f * A.y;
            float inv  = A.z;
            float sp = 0.0f, sc = A.x;     // sin(0), sin(a)
#pragma unroll
            for (int k = 0; k < N_RBF; k++) {
                sh_rbf[k][f] = sc * inv;
                float nx = twoc * sc - sp;
                sp = sc; sc = nx;
            }
            sh_rd0[f] = A.w;
            sh_rd1[f] = B.x;
            sh_rd2[f] = B.y;
            sh_src[f] = __float_as_int(B.z);
            sh_typ[f] = __float_as_int(B.w);
        }
        __syncthreads();

        // phase 2: walk node runs inside this chunk (all runs quad-aligned)
        int ec = 0;
        while (ec < nch) {
            int ndend = s_bnd[nd + 1];                       // global padded end
            int run = min(ndend - base, nch) - ec;           // multiple of 4
            for (int e = ec; e < ec + run; e += 4) {
                int4 s4 = *reinterpret_cast<const int4*>(&sh_src[e]);
                int4 t4 = *reinterpret_cast<const int4*>(&sh_typ[e]);
                const float* phA = g_phi + t4.x * F3;
                const float* phB = g_phi + t4.y * F3;
                const float* phC = g_phi + t4.z * F3;
                const float* phD = g_phi + t4.w * F3;
                float pA0 = phA[f], pA1 = phA[F_DIM + f], pA2 = phA[2 * F_DIM + f];
                float pB0 = phB[f], pB1 = phB[F_DIM + f], pB2 = phB[2 * F_DIM + f];
                float pC0 = phC[f], pC1 = phC[F_DIM + f], pC2 = phC[2 * F_DIM + f];
                float pD0 = phD[f], pD1 = phD[F_DIM + f], pD2 = phD[2 * F_DIM + f];
                const float* eqA = eq + (size_t)s4.x * F3 + f * 3;
                const float* eqB = eq + (size_t)s4.y * F3 + f * 3;
                const float* eqC = eq + (size_t)s4.z * F3 + f * 3;
                const float* eqD = eq + (size_t)s4.w * F3 + f * 3;
                float eA0 = eqA[0], eA1 = eqA[1], eA2 = eqA[2];
                float eB0 = eqB[0], eB1 = eqB[1], eB2 = eqB[2];
                float eC0 = eqC[0], eC1 = eqC[1], eC2 = eqC[2];
                float eD0 = eqD[0], eD1 = eqD[1], eD2 = eqD[2];
                float4 rdx = *reinterpret_cast<const float4*>(&sh_rd0[e]);
                float4 rdy = *reinterpret_cast<const float4*>(&sh_rd1[e]);
                float4 rdz = *reinterpret_cast<const float4*>(&sh_rd2[e]);

                float WA0 = br0, WA1 = br1, WA2 = br2;
                float WB0 = br0, WB1 = br1, WB2 = br2;
                float WC0 = br0, WC1 = br1, WC2 = br2;
                float WD0 = br0, WD1 = br1, WD2 = br2;
#pragma unroll
                for (int k = 0; k < N_RBF; k++) {
                    float4 r4 = *reinterpret_cast<const float4*>(&sh_rbf[k][e]);
                    WA0 = fmaf(r4.x, wr0[k], WA0);
                    WA1 = fmaf(r4.x, wr1[k], WA1);
                    WA2 = fmaf(r4.x, wr2[k], WA2);
                    WB0 = fmaf(r4.y, wr0[k], WB0);
                    WB1 = fmaf(r4.y, wr1[k], WB1);
                    WB2 = fmaf(r4.y, wr2[k], WB2);
                    WC0 = fmaf(r4.z, wr0[k], WC0);
                    WC1 = fmaf(r4.z, wr1[k], WC1);
                    WC2 = fmaf(r4.z, wr2[k], WC2);
                    WD0 = fmaf(r4.w, wr0[k], WD0);
                    WD1 = fmaf(r4.w, wr1[k], WD1);
                    WD2 = fmaf(r4.w, wr2[k], WD2);
                }
                float sA1 = pA1 * WA1, sA2 = pA2 * WA2;
                float sB1 = pB1 * WB1, sB2 = pB2 * WB2;
                float sC1 = pC1 * WC1, sC2 = pC2 * WC2;
                float sD1 = pD1 * WD1, sD2 = pD2 * WD2;
                acc0 = fmaf(pA0, WA0, acc0);
                acc0 = fmaf(pB0, WB0, acc0);
                acc0 = fmaf(pC0, WC0, acc0);
                acc0 = fmaf(pD0, WD0, acc0);
                aq0 = fmaf(eA0, sA1, fmaf(sA2, rdx.x, aq0));
                aq1 = fmaf(eA1, sA1, fmaf(sA2, rdy.x, aq1));
                aq2 = fmaf(eA2, sA1, fmaf(sA2, rdz.x, aq2));
                aq0 = fmaf(eB0, sB1, fmaf(sB2, rdx.y, aq0));
                aq1 = fmaf(eB1, sB1, fmaf(sB2, rdy.y, aq1));
                aq2 = fmaf(eB2, sB1, fmaf(sB2, rdz.y, aq2));
                aq0 = fmaf(eC0, sC1, fmaf(sC2, rdx.z, aq0));
                aq1 = fmaf(eC1, sC1, fmaf(sC2, rdy.z, aq1));
                aq2 = fmaf(eC2, sC1, fmaf(sC2, rdz.z, aq2));
                aq0 = fmaf(eD0, sD1, fmaf(sD2, rdx.w, aq0));
                aq1 = fmaf(eD1, sD1, fmaf(sD2, rdy.w, aq1));
                aq2 = fmaf(eD2, sD1, fmaf(sD2, rdz.w, aq2));
            }
            ec += run;
            if (base + ec == ndend) {
                // close node nb0+nd
                int node = nb0 + nd;
                int zi = __ldg(&z[node]);
                out_emb[node * F_DIM + f] = emb_table[zi * F_DIM + f] + acc0;
                const float* ei = eq     + (size_t)node * F3 + f * 3;
                float*       oe = out_eq + (size_t)node * F3 + f * 3;
                oe[0] = ei[0] + aq0;
                oe[1] = ei[1] + aq1;
                oe[2] = ei[2] + aq2;
                acc0 = aq0 = aq1 = aq2 = 0.f;
                nd++;
            }
        }
        __syncthreads();
    }

    // flush trailing empty nodes (zero-degree): out = input
    while (nd < NPB) {
        int node = nb0 + nd;
        int zi = __ldg(&z[node]);
        out_emb[node * F_DIM + f] = emb_table[zi * F_DIM + f];
        const float* ei = eq     + (size_t)node * F3 + f * 3;
        float*       oe = out_eq + (size_t)node * F3 + f * 3;
        oe[0] = ei[0];
        oe[1] = ei[1];
        oe[2] = ei[2];
        nd++;
    }
}

// ---------------------------------------------------------
extern "C" void kernel_launch(void* const* d_in, const int* in_sizes, int n_in,
                              void* d_out, int out_size) {
    const float* pos       = (const float*)d_in[0];
    const float* eq        = (const float*)d_in[1];
    const float* emb_table = (const float*)d_in[2];
    const float* w_phi1    = (const float*)d_in[3];
    const float* b_phi1    = (const float*)d_in[4];
    const float* w_phi2    = (const float*)d_in[5];
    const float* b_phi2    = (const float*)d_in[6];
    const float* w_rbf     = (const float*)d_in[7];
    const float* b_rbf     = (const float*)d_in[8];
    const int*   z         = (const int*)d_in[9];
    const int*   edge_src  = (const int*)d_in[10];
    const int*   edge_dst  = (const int*)d_in[11];

    float* out     = (float*)d_out;
    float* out_emb = out;                                  // [N, 128]
    float* out_eq  = out + (size_t)N_NODES * F_DIM;        // [N, 128, 3]

    pre_kernel<<<HIST_NB + PHI_NB, 256>>>(edge_dst, emb_table, w_phi1, b_phi1,
                                          w_phi2, b_phi2);

    cudaLaunchAttribute attr[1];
    attr[0].id = cudaLaunchAttributeProgrammaticStreamSerialization;
    attr[0].val.programmaticStreamSerializationAllowed = 1;

    {   // scan (PDL)
        cudaLaunchConfig_t cfg = {};
        cfg.gridDim = dim3(SCAN_NB);
        cfg.blockDim = dim3(SCAN_B);
        cfg.attrs = attr;
        cfg.numAttrs = 1;
        cudaLaunchKernelEx(&cfg, scan_kernel);
    }
    {   // sg (PDL)
        cudaLaunchConfig_t cfg = {};
        cfg.gridDim = dim3(HIST_NB);
        cfg.blockDim = dim3(256);
        cfg.attrs = attr;
        cfg.numAttrs = 1;
        cudaLaunchKernelEx(&cfg, sg_kernel, pos, z, edge_src, edge_dst);
    }
    {   // main (PDL)
        cudaLaunchConfig_t cfg = {};
        cfg.gridDim = dim3(MAIN_NB);
        cfg.blockDim = dim3(128);
        cfg.attrs = attr;
        cfg.numAttrs = 1;
        cudaLaunchKernelEx(&cfg, main_kernel, eq, emb_table, w_rbf, b_rbf, z,
                           out_emb, out_eq);
    }
}